// round 2
// baseline (speedup 1.0000x reference)
#include <cuda_runtime.h>
#include <math.h>

#define NW      14
#define NSTATE  16384          // 2^14
#define LAYERS  3
#define THREADS 1024
#define PER     16             // amplitudes per thread (16384/1024)
#define PAIRS   8              // pairs per thread per gate (8192/1024)

// aux layout (floats):
//  [0..167]    gate coefs: (ca, sa, cos(phi), sin(phi)) per (layer,wire)
//  [168..181]  cos(x/2) per wire (RX encoding)
//  [182..195]  sin(x/2) per wire
//  [200..327]  Tlo[128]  weight table, low 7 index bits
//  [328..455]  Thi[128]  weight table, high 7 index bits
//  [456..487]  per-warp reduction partials
#define AUX_FLOATS 512
#define SMEM_BYTES ((2 * NSTATE + AUX_FLOATS) * sizeof(float))

__global__ __launch_bounds__(THREADS, 1)
void qsim_kernel(const float* __restrict__ state,   // [256,14]
                 const float* __restrict__ vp,      // [3,14,3]
                 const float* __restrict__ hw,      // [14]
                 const float* __restrict__ hb,      // [1]
                 float* __restrict__ out)           // [256]
{
    extern __shared__ float sm[];
    float* re  = sm;
    float* im  = sm + NSTATE;
    float* aux = sm + 2 * NSTATE;

    const int tid = threadIdx.x;
    const int b   = blockIdx.x;

    // ---- precompute: gate coefs, encoding cos/sin, head weight tables ----
    if (tid < LAYERS * NW) {
        float a  = 0.5f * vp[tid * 3 + 0];
        float th = 0.5f * vp[tid * 3 + 1];
        float ca, sa, cf, sf;
        sincosf(a,  &sa, &ca);
        sincosf(th, &sf, &cf);
        aux[tid * 4 + 0] = ca;
        aux[tid * 4 + 1] = sa;
        aux[tid * 4 + 2] = cf;
        aux[tid * 4 + 3] = sf;
    } else if (tid >= 64 && tid < 64 + NW) {
        int w = tid - 64;
        float h = 0.5f * state[b * NW + w];
        float c, s;
        sincosf(h, &s, &c);
        aux[168 + w] = c;
        aux[182 + w] = s;
    } else if (tid >= 128 && tid < 256) {
        // Tlo: bit position p (0..6) of the index corresponds to wire 13-p
        int x = tid - 128;
        float acc = 0.f;
        #pragma unroll
        for (int p = 0; p < 7; p++)
            acc += (((x >> p) & 1) ? -1.f : 1.f) * hw[13 - p];
        aux[200 + x] = acc;
    } else if (tid >= 256 && tid < 384) {
        // Thi: bit position p (0..6) of (index>>7) corresponds to wire 6-p
        int x = tid - 256;
        float acc = 0.f;
        #pragma unroll
        for (int p = 0; p < 7; p++)
            acc += (((x >> p) & 1) ? -1.f : 1.f) * hw[6 - p];
        aux[328 + x] = acc;
    }
    __syncthreads();

    // ---- init: RX-encoded product state ----
    // amp(idx) = prod_w (bit_w ? sin_w : cos_w) * (-i)^popc(idx)
    // wire w lives at bit position 13-w (wire 0 = MSB)
    #pragma unroll
    for (int i = 0; i < PER; i++) {
        unsigned idx = tid + (i << 10);
        float prod = 1.f;
        #pragma unroll
        for (int j = 0; j < NW; j++) {
            float c = aux[168 + 13 - j];
            float s = aux[182 + 13 - j];
            prod *= ((idx >> j) & 1u) ? s : c;
        }
        int k = __popc(idx) & 3;
        float sgn = (k == 1 || k == 2) ? -prod : prod;
        bool odd = (k & 1);
        re[idx] = odd ? 0.f : sgn;
        im[idx] = odd ? sgn : 0.f;
    }
    __syncthreads();

    // ---- variational layers ----
    for (int l = 0; l < LAYERS; l++) {
        for (int w = 0; w < NW; w++) {
            int g = (l * NW + w) * 4;
            float ca = aux[g + 0];
            float sa = aux[g + 1];
            float cf = aux[g + 2];
            float sf = aux[g + 3];
            const int k = 13 - w;
            const unsigned m = 1u << k;
            const unsigned lomask = m - 1u;
            #pragma unroll
            for (int it = 0; it < PAIRS; it++) {
                unsigned p  = tid + (it << 10);
                unsigned lo = p & lomask;
                unsigned i0 = ((p ^ lo) << 1) | lo;
                unsigned i1 = i0 | m;
                float a0r = re[i0], a0i = im[i0];
                float a1r = re[i1], a1i = im[i1];
                // RY
                float t0r = ca * a0r - sa * a1r;
                float t0i = ca * a0i - sa * a1i;
                float t1r = sa * a0r + ca * a1r;
                float t1i = sa * a0i + ca * a1i;
                // RZ: row0 *= e^{-i phi}, row1 *= e^{+i phi}
                re[i0] = t0r * cf + t0i * sf;
                im[i0] = t0i * cf - t0r * sf;
                re[i1] = t1r * cf - t1i * sf;
                im[i1] = t1i * cf + t1r * sf;
            }
            __syncthreads();
        }
        if (l < LAYERS - 1) {
            // CNOT chain == Gray-code permutation: psi_new[y] = psi_old[y ^ (y>>1)]
            float rr[PER], qq[PER];
            #pragma unroll
            for (int i = 0; i < PER; i++) {
                unsigned y   = tid + (i << 10);
                unsigned src = y ^ (y >> 1);
                rr[i] = re[src];
                qq[i] = im[src];
            }
            __syncthreads();
            #pragma unroll
            for (int i = 0; i < PER; i++) {
                unsigned y = tid + (i << 10);
                re[y] = rr[i];
                im[y] = qq[i];
            }
            __syncthreads();
        }
    }

    // ---- expectation + linear head (last layer's CNOT perm folded in) ----
    // stored index y corresponds to final basis index g = grayDecode(y)
    float acc = 0.f;
    #pragma unroll
    for (int i = 0; i < PER; i++) {
        unsigned y = tid + (i << 10);
        unsigned gidx = y;
        gidx ^= gidx >> 1;
        gidx ^= gidx >> 2;
        gidx ^= gidx >> 4;
        gidx ^= gidx >> 8;
        float wt = aux[200 + (gidx & 127u)] + aux[328 + ((gidx >> 7) & 127u)];
        float r = re[y], q = im[y];
        acc = fmaf(fmaf(r, r, q * q), wt, acc);
    }
    #pragma unroll
    for (int o = 16; o; o >>= 1)
        acc += __shfl_xor_sync(0xffffffffu, acc, o);
    if ((tid & 31) == 0)
        aux[456 + (tid >> 5)] = acc;
    __syncthreads();
    if (tid < 32) {
        float v = aux[456 + tid];
        #pragma unroll
        for (int o = 16; o; o >>= 1)
            v += __shfl_xor_sync(0xffffffffu, v, o);
        if (tid == 0)
            out[b] = v + hb[0];
    }
}

extern "C" void kernel_launch(void* const* d_in, const int* in_sizes, int n_in,
                              void* d_out, int out_size)
{
    const float* state = (const float*)d_in[0];  // [256,14]
    const float* vp    = (const float*)d_in[1];  // [3,14,3]
    const float* hw    = (const float*)d_in[2];  // [14]
    const float* hb    = (const float*)d_in[3];  // [1]
    float* out = (float*)d_out;

    cudaFuncSetAttribute(qsim_kernel,
                         cudaFuncAttributeMaxDynamicSharedMemorySize,
                         (int)SMEM_BYTES);
    qsim_kernel<<<256, THREADS, SMEM_BYTES>>>(state, vp, hw, hb, out);
}

// round 3
// speedup vs baseline: 1.6681x; 1.6681x over previous
#include <cuda_runtime.h>
#include <math.h>

typedef unsigned long long ull;

#define THREADS 1024
#define NSTATE  16384

// aux float offsets (aux = sm + 2*NSTATE floats)
#define OF_GATE 0      // 42 gates * 12 floats (packed coef pairs)
#define OF_ENC_C 512   // 14
#define OF_ENC_S 528   // 14
#define OF_RTAB 544    // 16
#define OF_TLO  576    // 128
#define OF_THI  704    // 128
#define OF_WARP 832    // 32
#define AUXF    864
#define SMEM_BYTES ((2 * NSTATE + AUXF) * sizeof(float))

__device__ __forceinline__ ull pk(float lo, float hi) {
    ull r; asm("mov.b64 %0, {%1,%2};" : "=l"(r) : "f"(lo), "f"(hi)); return r;
}
__device__ __forceinline__ void upk(ull v, float& lo, float& hi) {
    asm("mov.b64 {%0,%1}, %2;" : "=f"(lo), "=f"(hi) : "l"(v));
}
__device__ __forceinline__ ull swap2(ull v) {
    float lo, hi;
    asm("mov.b64 {%0,%1}, %2;" : "=f"(lo), "=f"(hi) : "l"(v));
    ull r; asm("mov.b64 %0, {%1,%2};" : "=l"(r) : "f"(hi), "f"(lo)); return r;
}
__device__ __forceinline__ ull mul2(ull a, ull b) {
    ull d; asm("mul.rn.f32x2 %0, %1, %2;" : "=l"(d) : "l"(a), "l"(b)); return d;
}
__device__ __forceinline__ ull fma2(ull a, ull b, ull c) {
    ull d; asm("fma.rn.f32x2 %0, %1, %2, %3;" : "=l"(d) : "l"(a), "l"(b), "l"(c)); return d;
}

// Fused RY+RZ on a pair of packed (re,im) amplitudes.
// T0 = ca*A0 - sa*A1 ; T1 = sa*A0 + ca*A1 ; then row0 *= e^{-i phi}, row1 *= e^{+i phi}
__device__ __forceinline__ void pair_gate(ull& A0, ull& A1,
                                          ull ca2, ull nsa2, ull sa2,
                                          ull cf2, ull ph0, ull ph1) {
    ull T0 = fma2(nsa2, A1, mul2(ca2, A0));
    ull T1 = fma2(sa2,  A0, mul2(ca2, A1));
    A0 = fma2(ph0, swap2(T0), mul2(cf2, T0));
    A1 = fma2(ph1, swap2(T1), mul2(cf2, T1));
}

// Same gate when the partner amplitude lives in another lane (lane-bit wire).
__device__ __forceinline__ void shfl_gate(ull& A, unsigned mask,
                                          ull ca2, ull sp, ull cf2, ull ph) {
    ull P = __shfl_xor_sync(0xffffffffu, A, mask);
    ull T = fma2(sp, P, mul2(ca2, A));
    A = fma2(ph, swap2(T), mul2(cf2, T));
}

__global__ __launch_bounds__(THREADS, 1)
void qsim_kernel(const float* __restrict__ state,   // [256,14]
                 const float* __restrict__ vp,      // [3,14,3]
                 const float* __restrict__ hw,      // [14]
                 const float* __restrict__ hb,      // [1]
                 float* __restrict__ out)           // [256]
{
    extern __shared__ float sm[];
    ull*   psi = (ull*)sm;                 // 16384 packed (re,im)
    float* aux = sm + 2 * NSTATE;

    const int tid  = threadIdx.x;
    const int lane = tid & 31;
    const int wa   = tid >> 5;

    // ---- phase 1: gate coef packs, encoding cos/sin, weight tables ----
    if (tid < 42) {
        float a  = 0.5f * vp[tid * 3 + 0];
        float th = 0.5f * vp[tid * 3 + 1];
        float ca, sa, cf, sf;
        sincosf(a,  &sa, &ca);
        sincosf(th, &sf, &cf);
        float* g = aux + OF_GATE + tid * 12;
        g[0] = ca;  g[1] = ca;          // ca2
        g[2] = -sa; g[3] = -sa;         // nsa2
        g[4] = sa;  g[5] = sa;          // sa2
        g[6] = cf;  g[7] = cf;          // cf2
        g[8] = sf;  g[9] = -sf;         // ph0 = (sf,-sf)
        g[10] = -sf; g[11] = sf;        // ph1 = (-sf,sf)
    } else if (tid >= 64 && tid < 78) {
        int w = tid - 64;
        float h = 0.5f * state[blockIdx.x * 14 + w];
        float c, s;
        sincosf(h, &s, &c);
        aux[OF_ENC_C + w] = c;
        aux[OF_ENC_S + w] = s;
    } else if (tid >= 128 && tid < 256) {
        int x = tid - 128;
        float a2 = 0.f;
        #pragma unroll
        for (int p = 0; p < 7; p++)
            a2 += (((x >> p) & 1) ? -1.f : 1.f) * hw[13 - p];
        aux[OF_TLO + x] = a2;
    } else if (tid >= 256 && tid < 384) {
        int x = tid - 256;
        float a2 = 0.f;
        #pragma unroll
        for (int p = 0; p < 7; p++)
            a2 += (((x >> p) & 1) ? -1.f : 1.f) * hw[6 - p];
        aux[OF_THI + x] = a2;
    }
    __syncthreads();

    // rtab: product of factors for idx bits 10..13 (wires 3..0)
    if (tid < 16) {
        float m = 1.f;
        #pragma unroll
        for (int j = 0; j < 4; j++)
            m *= ((tid >> j) & 1) ? aux[OF_ENC_S + 3 - j] : aux[OF_ENC_C + 3 - j];
        aux[OF_RTAB + tid] = m;
    }
    // per-thread base product over tid bits 0..9 (wires 13..4)
    float P = 1.f;
    #pragma unroll
    for (int j = 0; j < 10; j++)
        P *= ((tid >> j) & 1) ? aux[OF_ENC_S + 13 - j] : aux[OF_ENC_C + 13 - j];
    int pt = __popc(tid);
    __syncthreads();

    // ---- init: RX product state, written directly ----
    #pragma unroll
    for (int r = 0; r < 16; r++) {
        float mag = P * aux[OF_RTAB + r];
        int k = (pt + __popc(r)) & 3;
        float sg = (k == 1 || k == 2) ? -mag : mag;
        float re_ = (k & 1) ? 0.f : sg;
        float im_ = (k & 1) ? sg : 0.f;
        psi[tid | (r << 10)] = pk(re_, im_);
    }
    __syncthreads();

    float acc = 0.f;

    #pragma unroll 1
    for (int l = 0; l < 3; l++) {
        // ======== Pass A: locals = bits 10-13 ========
        // read (gray-folded CNOT perm of previous layer for l>0)
        ull A[16];
        #pragma unroll
        for (int r = 0; r < 16; r++) {
            int e = tid | (r << 10);
            int src = l ? (e ^ (e >> 1)) : e;
            A[r] = psi[src];
        }
        if (l) __syncthreads();   // gather != scatter: drain reads before writes

        // shfl gates: wires 9..13 (idx bits 4..0 = lane bits)
        #pragma unroll
        for (int w = 9; w < 14; w++) {
            const ull* g = (const ull*)(aux + OF_GATE + (l * 14 + w) * 12);
            int bit = 13 - w;
            int b = (lane >> bit) & 1;
            ull ca2 = g[0], cf2 = g[3];
            ull sp = b ? g[2] : g[1];
            ull ph = b ? g[5] : g[4];
            unsigned mask = 1u << bit;
            #pragma unroll
            for (int r = 0; r < 16; r++)
                shfl_gate(A[r], mask, ca2, sp, cf2, ph);
        }
        // reg gates: wires 0..3 (local bit j = 3-w)
        #pragma unroll
        for (int w = 0; w < 4; w++) {
            const ull* g = (const ull*)(aux + OF_GATE + (l * 14 + w) * 12);
            int bj = 1 << (3 - w);
            #pragma unroll
            for (int r = 0; r < 16; r++)
                if (!(r & bj))
                    pair_gate(A[r], A[r | bj], g[0], g[1], g[2], g[3], g[4], g[5]);
        }
        #pragma unroll
        for (int r = 0; r < 16; r++)
            psi[tid | (r << 10)] = A[r];
        __syncthreads();

        // ======== Pass B: locals = bits 6-9, wires 4..7 ========
        {
            int base = lane | ((wa & 1) << 5) | ((wa >> 1) << 10);
            ull Bv[16];
            #pragma unroll
            for (int r = 0; r < 16; r++)
                Bv[r] = psi[base | (r << 6)];
            #pragma unroll
            for (int w = 4; w < 8; w++) {
                const ull* g = (const ull*)(aux + OF_GATE + (l * 14 + w) * 12);
                int bj = 1 << (7 - w);
                #pragma unroll
                for (int r = 0; r < 16; r++)
                    if (!(r & bj))
                        pair_gate(Bv[r], Bv[r | bj], g[0], g[1], g[2], g[3], g[4], g[5]);
            }
            #pragma unroll
            for (int r = 0; r < 16; r++)
                psi[base | (r << 6)] = Bv[r];
            __syncthreads();
        }

        // ======== Pass C: locals = bits 5-8, wire 8 (local bit 0) ========
        {
            int base = lane | (wa << 9);
            ull Cv[16];
            #pragma unroll
            for (int r = 0; r < 16; r++)
                Cv[r] = psi[base | (r << 5)];
            const ull* g = (const ull*)(aux + OF_GATE + (l * 14 + 8) * 12);
            #pragma unroll
            for (int r = 0; r < 16; r += 2)
                pair_gate(Cv[r], Cv[r + 1], g[0], g[1], g[2], g[3], g[4], g[5]);

            if (l < 2) {
                #pragma unroll
                for (int r = 0; r < 16; r++)
                    psi[base | (r << 5)] = Cv[r];
                __syncthreads();
            } else {
                // fold final CNOT perm + <Z> + linear head: stored e -> basis grayDecode(e)
                #pragma unroll
                for (int r = 0; r < 16; r++) {
                    int e = base | (r << 5);
                    int gg = e;
                    gg ^= gg >> 1; gg ^= gg >> 2; gg ^= gg >> 4; gg ^= gg >> 8;
                    float wt = aux[OF_TLO + (gg & 127)] + aux[OF_THI + ((gg >> 7) & 127)];
                    float x, y; upk(Cv[r], x, y);
                    acc = fmaf(fmaf(x, x, y * y), wt, acc);
                }
            }
        }
    }

    // ---- block reduction ----
    #pragma unroll
    for (int o = 16; o; o >>= 1)
        acc += __shfl_xor_sync(0xffffffffu, acc, o);
    if (lane == 0)
        aux[OF_WARP + wa] = acc;
    __syncthreads();
    if (tid < 32) {
        float v = aux[OF_WARP + tid];
        #pragma unroll
        for (int o = 16; o; o >>= 1)
            v += __shfl_xor_sync(0xffffffffu, v, o);
        if (tid == 0)
            out[blockIdx.x] = v + hb[0];
    }
}

extern "C" void kernel_launch(void* const* d_in, const int* in_sizes, int n_in,
                              void* d_out, int out_size)
{
    const float* state = (const float*)d_in[0];
    const float* vp    = (const float*)d_in[1];
    const float* hw    = (const float*)d_in[2];
    const float* hb    = (const float*)d_in[3];
    float* out = (float*)d_out;

    cudaFuncSetAttribute(qsim_kernel,
                         cudaFuncAttributeMaxDynamicSharedMemorySize,
                         (int)SMEM_BYTES);
    qsim_kernel<<<256, THREADS, SMEM_BYTES>>>(state, vp, hw, hb, out);
}